// round 1
// baseline (speedup 1.0000x reference)
#include <cuda_runtime.h>

#define NG   4
#define NB   4
#define LQ   512
#define NC   768
#define NH   12
#define DH   64
#define MPG  (NB*LQ)           // 2048 rows per group

// Scratch: Q/K/V in head-major layout [((g*NB+b)*NH+h)*LQ + l]*DH + dh
__device__ float g_q[NG*NB*NH*LQ*DH];
__device__ float g_k[NG*NB*NH*LQ*DH];
__device__ float g_v[NG*NB*NH*LQ*DH];

// ---------------------------------------------------------------------------
// QKV projection GEMM: out[g, t, d] = hs[g, t, :] . W[g, :, d] + bias[g, d]
// scattered into head-major layout. 64x64 tile, k-chunk 16, 4x4 microtile.
// grid = (NC/64, MPG/64, NG), block = 256
// ---------------------------------------------------------------------------
__global__ __launch_bounds__(256) void qkv_gemm_kernel(
    const float* __restrict__ hs, const float* __restrict__ W,
    const float* __restrict__ bias, float* __restrict__ outp)
{
    __shared__ float As[64 * 16];
    __shared__ float Bs[16 * 64];

    const int g  = blockIdx.z;
    const int m0 = blockIdx.y * 64;
    const int n0 = blockIdx.x * 64;
    const int tid = threadIdx.x;
    const int tx = tid & 15;        // 0..15 -> 4 output cols each
    const int ty = tid >> 4;        // 0..15 -> 4 output rows each

    const float* hsg = hs + (size_t)g * MPG * NC;
    const float* Wg  = W  + (size_t)g * NC * NC;

    float4 acc[4];
    #pragma unroll
    for (int i = 0; i < 4; i++) acc[i] = make_float4(0.f, 0.f, 0.f, 0.f);

    for (int k0 = 0; k0 < NC; k0 += 16) {
        // A tile 64x16 (one float4 per thread, fully coalesced)
        {
            const int r  = tid >> 2;
            const int c4 = (tid & 3) * 4;
            *(float4*)(As + r * 16 + c4) =
                *(const float4*)(hsg + (size_t)(m0 + r) * NC + k0 + c4);
        }
        // B tile 16x64 (one float4 per thread, fully coalesced)
        {
            const int r  = tid >> 4;
            const int c4 = (tid & 15) * 4;
            *(float4*)(Bs + r * 64 + c4) =
                *(const float4*)(Wg + (size_t)(k0 + r) * NC + n0 + c4);
        }
        __syncthreads();

        #pragma unroll
        for (int kk = 0; kk < 16; kk++) {
            const float4 b = *(const float4*)(Bs + kk * 64 + tx * 4);
            #pragma unroll
            for (int ii = 0; ii < 4; ii++) {
                const float a = As[(ty * 4 + ii) * 16 + kk];
                acc[ii].x += a * b.x;
                acc[ii].y += a * b.y;
                acc[ii].z += a * b.z;
                acc[ii].w += a * b.w;
            }
        }
        __syncthreads();
    }

    // epilogue: add bias, scatter to head-major layout
    const float* bg = bias + (size_t)g * NC;
    #pragma unroll
    for (int ii = 0; ii < 4; ii++) {
        const int t = m0 + ty * 4 + ii;
        const int b = t / LQ;
        const int l = t % LQ;
        const float* av = (const float*)&acc[ii];
        #pragma unroll
        for (int jj = 0; jj < 4; jj++) {
            const int d  = n0 + tx * 4 + jj;
            const int h  = d / DH;
            const int dh = d % DH;
            outp[((((size_t)g * NB + b) * NH + h) * LQ + l) * DH + dh] =
                av[jj] + bg[d];
        }
    }
}

// ---------------------------------------------------------------------------
// Attention: one block per (gbh, 32-row query tile). block = 256 (8 warps).
// smem: Qs[32][64] | S[32][512] | KV[64][65] (K transposed+padded / V natural)
// ---------------------------------------------------------------------------
#define QT 32
#define SMEM_FLOATS (QT*DH + QT*LQ + 64*65)   // 22592 floats = 90368 B

__global__ __launch_bounds__(256) void attn_kernel(
    const float* __restrict__ qg, const float* __restrict__ kg,
    const float* __restrict__ vg, const float* __restrict__ mask,
    float* __restrict__ out)
{
    extern __shared__ float smem[];
    float* Qs = smem;                // [QT][DH]
    float* S  = smem + QT * DH;      // [QT][LQ]
    float* KV = S + QT * LQ;         // [64][65] (K) or [64][64] (V)

    const int gbh = blockIdx.y;          // ((g*NB+b)*NH + h)
    const int l0  = blockIdx.x * QT;
    const int h   = gbh % NH;
    const int gb  = gbh / NH;            // g*NB + b
    const int tid  = threadIdx.x;
    const int lane = tid & 31;
    const int warp = tid >> 5;           // 0..7 -> 4 query rows each

    const float* Q  = qg + (size_t)gbh * LQ * DH;
    const float* K  = kg + (size_t)gbh * LQ * DH;
    const float* V  = vg + (size_t)gbh * LQ * DH;
    const float* mk = mask + (size_t)gb * LQ;

    // load Q tile (natural layout)
    for (int idx = tid; idx < QT * DH; idx += 256)
        Qs[idx] = Q[(size_t)l0 * DH + idx];

    const float scale = 0.125f;   // 1/sqrt(64)

    // ---- phase 1: S[i][m] = Q[i].K[m]  (raw, scale applied in softmax) ----
    for (int kt = 0; kt < LQ / 64; kt++) {
        const int m0k = kt * 64;
        __syncthreads();                       // also covers Qs on first iter
        // K tile transposed: KV[c*65 + m] = K[m0k+m][c]
        for (int idx = tid; idx < 64 * 64; idx += 256) {
            const int m = idx >> 6, c = idx & 63;
            KV[c * 65 + m] = K[(size_t)(m0k + m) * DH + c];
        }
        __syncthreads();

        float acc[4][2];
        #pragma unroll
        for (int ii = 0; ii < 4; ii++) { acc[ii][0] = 0.f; acc[ii][1] = 0.f; }

        #pragma unroll 8
        for (int c = 0; c < 64; c++) {
            const float k0v = KV[c * 65 + lane * 2 + 0];
            const float k1v = KV[c * 65 + lane * 2 + 1];
            #pragma unroll
            for (int ii = 0; ii < 4; ii++) {
                const float qv = Qs[(warp * 4 + ii) * DH + c];  // warp broadcast
                acc[ii][0] += qv * k0v;
                acc[ii][1] += qv * k1v;
            }
        }
        #pragma unroll
        for (int ii = 0; ii < 4; ii++) {
            S[(warp * 4 + ii) * LQ + m0k + lane * 2 + 0] = acc[ii][0];
            S[(warp * 4 + ii) * LQ + m0k + lane * 2 + 1] = acc[ii][1];
        }
    }
    __syncthreads();

    // ---- phase 2: softmax per row (warp handles 4 rows) ----
    #pragma unroll
    for (int rr = 0; rr < 4; rr++) {
        float* Sr = S + (warp * 4 + rr) * LQ;
        float mx = -1e30f;
        for (int j = lane; j < LQ; j += 32) {
            const float v = Sr[j] * scale + mk[j];
            Sr[j] = v;
            mx = fmaxf(mx, v);
        }
        #pragma unroll
        for (int o = 16; o; o >>= 1) mx = fmaxf(mx, __shfl_xor_sync(0xFFFFFFFFu, mx, o));
        float sum = 0.f;
        for (int j = lane; j < LQ; j += 32) {
            const float e = __expf(Sr[j] - mx);
            Sr[j] = e;
            sum += e;
        }
        #pragma unroll
        for (int o = 16; o; o >>= 1) sum += __shfl_xor_sync(0xFFFFFFFFu, sum, o);
        const float inv = 1.0f / sum;
        for (int j = lane; j < LQ; j += 32) Sr[j] *= inv;
    }

    // ---- phase 3: ctx = P @ V ----
    float acc3[4][2];
    #pragma unroll
    for (int ii = 0; ii < 4; ii++) { acc3[ii][0] = 0.f; acc3[ii][1] = 0.f; }

    for (int kt = 0; kt < LQ / 64; kt++) {
        const int m0k = kt * 64;
        __syncthreads();
        // V tile natural layout [m][d]
        for (int idx = tid; idx < 64 * 64; idx += 256)
            KV[idx] = V[(size_t)m0k * DH + idx];
        __syncthreads();

        #pragma unroll 8
        for (int mm = 0; mm < 64; mm++) {
            const float v0 = KV[mm * 64 + lane * 2 + 0];
            const float v1 = KV[mm * 64 + lane * 2 + 1];
            #pragma unroll
            for (int ii = 0; ii < 4; ii++) {
                const float p = S[(warp * 4 + ii) * LQ + m0k + mm]; // broadcast
                acc3[ii][0] += p * v0;
                acc3[ii][1] += p * v1;
            }
        }
    }

    // write: out[gb, l, h*DH + dh]
    #pragma unroll
    for (int ii = 0; ii < 4; ii++) {
        const size_t row = ((size_t)gb * LQ + l0 + warp * 4 + ii) * NC + h * DH;
        out[row + lane * 2 + 0] = acc3[ii][0];
        out[row + lane * 2 + 1] = acc3[ii][1];
    }
}

// ---------------------------------------------------------------------------
extern "C" void kernel_launch(void* const* d_in, const int* in_sizes, int n_in,
                              void* d_out, int out_size)
{
    (void)in_sizes; (void)n_in; (void)out_size;
    const float* hs   = (const float*)d_in[0];
    const float* mask = (const float*)d_in[1];
    const float* qw   = (const float*)d_in[2];
    const float* qb   = (const float*)d_in[3];
    const float* kw   = (const float*)d_in[4];
    const float* kb   = (const float*)d_in[5];
    const float* vw   = (const float*)d_in[6];
    const float* vb   = (const float*)d_in[7];
    float* out = (float*)d_out;

    float *qp, *kp, *vp;
    cudaGetSymbolAddress((void**)&qp, g_q);
    cudaGetSymbolAddress((void**)&kp, g_k);
    cudaGetSymbolAddress((void**)&vp, g_v);

    dim3 ggrid(NC / 64, MPG / 64, NG);
    qkv_gemm_kernel<<<ggrid, 256>>>(hs, qw, qb, qp);
    qkv_gemm_kernel<<<ggrid, 256>>>(hs, kw, kb, kp);
    qkv_gemm_kernel<<<ggrid, 256>>>(hs, vw, vb, vp);

    const int smem_bytes = SMEM_FLOATS * (int)sizeof(float);
    cudaFuncSetAttribute(attn_kernel,
                         cudaFuncAttributeMaxDynamicSharedMemorySize, smem_bytes);
    dim3 agrid(LQ / QT, NG * NB * NH);
    attn_kernel<<<agrid, 256, smem_bytes>>>(qp, kp, vp, mask, out);
}